// round 1
// baseline (speedup 1.0000x reference)
#include <cuda_runtime.h>

// out[i] = 2 * in[i], N = 100 floats. Pure launch-latency-bound.
// One block, 32 threads, float4 vectorized: 25 float4 loads/stores total.
__global__ void __launch_bounds__(32, 1) mul2_kernel(const float4* __restrict__ in,
                                                     float4* __restrict__ out) {
    int i = threadIdx.x;           // 0..31
    if (i < 25) {                  // 25 * 4 = 100 elements
        float4 v = in[i];
        v.x *= 2.0f; v.y *= 2.0f; v.z *= 2.0f; v.w *= 2.0f;
        out[i] = v;
    }
}

extern "C" void kernel_launch(void* const* d_in, const int* in_sizes, int n_in,
                              void* d_out, int out_size) {
    const float4* in = (const float4*)d_in[0];
    float4* out = (float4*)d_out;
    mul2_kernel<<<1, 32>>>(in, out);
}

// round 3
// speedup vs baseline: 1.2324x; 1.2324x over previous
#include <cuda_runtime.h>

// out[i] = 2 * in[i], N = 100 floats (25 float4). Launch-latency-bound.
// Exactly 25 threads: hardware lane-masks the partial warp, so no guard
// predicate is needed in SASS. One LDG.128 + one STG.128 per thread,
// MLP=25 in a single warp fully overlaps the DRAM/L2 round trip.
__global__ void __launch_bounds__(32, 1) mul2_kernel(const float4* __restrict__ in,
                                                     float4* __restrict__ out) {
    int i = threadIdx.x;           // 0..24, no bounds check needed
    float4 v = __ldg(&in[i]);
    v.x *= 2.0f; v.y *= 2.0f; v.z *= 2.0f; v.w *= 2.0f;
    // streaming store: skip L2 allocate bookkeeping on the write path
    asm volatile("st.global.cs.v4.f32 [%0], {%1, %2, %3, %4};"
                 :: "l"(&out[i]), "f"(v.x), "f"(v.y), "f"(v.z), "f"(v.w)
                 : "memory");
}

extern "C" void kernel_launch(void* const* d_in, const int* in_sizes, int n_in,
                              void* d_out, int out_size) {
    const float4* in = (const float4*)d_in[0];
    float4* out = (float4*)d_out;
    mul2_kernel<<<1, 25>>>(in, out);
}